// round 15
// baseline (speedup 1.0000x reference)
#include <cuda_runtime.h>
#include <cuda_bf16.h>
#include <cstdint>

#define N_NODES  30000
#define N_EDGES  300000
#define N_GRAPHS 128
#define DIM      128

// ---------------------------------------------------------------------------
// Scratch: __device__ globals, referenced ONLY from device code.
// ---------------------------------------------------------------------------
__device__ float g_bufA[(size_t)N_EDGES * 256];   // hidden ping
__device__ float g_bufB[(size_t)N_EDGES * 256];   // hidden pong
__device__ float g_agg[(size_t)N_NODES * DIM];    // scatter-sum of edges_out by col
__device__ float g_cnt[N_NODES];                  // edge count per node
__device__ float g_gsn[N_GRAPHS * DIM];           // per-graph node sums
__device__ float g_gse[N_GRAPHS * DIM];           // per-graph edge sums
__device__ float g_gcn[N_GRAPHS];                 // per-graph node counts
__device__ float g_gce[N_GRAPHS];                 // per-graph edge counts
__device__ float g_gin[N_GRAPHS * 384];           // global MLP input
__device__ float g_gh0[N_GRAPHS * 256];
__device__ float g_gh1[N_GRAPHS * 256];

__device__ __forceinline__ float* buf_ptr(int sel, float* def) {
    if (sel == 0) return g_bufA;
    if (sel == 1) return g_bufB;
    return def;
}
__device__ __forceinline__ const float* cbuf_ptr(int sel, const float* def) {
    if (sel == 0) return g_bufA;
    if (sel == 1) return g_bufB;
    if (sel == 2) return g_gin;
    if (sel == 3) return g_gh0;
    if (sel == 4) return g_gh1;
    return def;
}

// packed fp32x2 FMA
__device__ __forceinline__ void ffma2(unsigned long long& d,
                                      unsigned long long a,
                                      unsigned long long b) {
    asm("fma.rn.f32x2 %0, %1, %2, %0;" : "+l"(d) : "l"(a), "l"(b));
}

// ---------------------------------------------------------------------------
// Zero accumulators
// ---------------------------------------------------------------------------
#define NZ_AGG (N_NODES * DIM)
#define NZ_1   (NZ_AGG + N_NODES)
#define NZ_2   (NZ_1 + N_GRAPHS * DIM)
#define NZ_3   (NZ_2 + N_GRAPHS * DIM)
#define NZ_4   (NZ_3 + N_GRAPHS)
#define NZ_TOT (NZ_4 + N_GRAPHS)

__global__ void zero_all_kernel() {
    int i = blockIdx.x * blockDim.x + threadIdx.x;
    if (i < NZ_AGG)      g_agg[i] = 0.0f;
    else if (i < NZ_1)   g_cnt[i - NZ_AGG] = 0.0f;
    else if (i < NZ_2)   g_gsn[i - NZ_1] = 0.0f;
    else if (i < NZ_3)   g_gse[i - NZ_2] = 0.0f;
    else if (i < NZ_4)   g_gcn[i - NZ_3] = 0.0f;
    else if (i < NZ_TOT) g_gce[i - NZ_4] = 0.0f;
}

// ---------------------------------------------------------------------------
// Vec4 gathered X loads (section boundaries multiples of 128; k0 multiple of
// BK=16 -> branch uniform per slab; aligned LDG.128).
// ---------------------------------------------------------------------------
template <int MODE>
__device__ __forceinline__ float4 load_x4(
    int m, int k, const float* __restrict__ X, int ldx,
    const float* __restrict__ nodes,
    const int* __restrict__ erow, const int* __restrict__ ecol,
    const float* __restrict__ eattr,
    const float* __restrict__ u, const int* __restrict__ batch) {
    if (MODE == 0) {
        return *(const float4*)&X[(size_t)m * ldx + k];
    } else if (MODE == 1) {
        if (k < 128) {
            return *(const float4*)&nodes[(size_t)erow[m] * 128 + k];
        } else if (k < 256) {
            return *(const float4*)&nodes[(size_t)ecol[m] * 128 + (k - 128)];
        } else if (k < 384) {
            return *(const float4*)&eattr[(size_t)m * 128 + (k - 256)];
        } else {
            return *(const float4*)&u[batch[erow[m]] * 128 + (k - 384)];
        }
    } else {
        if (k < 128) {
            return *(const float4*)&nodes[(size_t)m * 128 + k];
        } else if (k < 256) {
            float r = __frcp_rn(fmaxf(g_cnt[m], 1.0f));
            float4 a = *(const float4*)&g_agg[(size_t)m * 128 + (k - 128)];
            return make_float4(a.x * r, a.y * r, a.z * r, a.w * r);
        } else {
            return *(const float4*)&u[batch[m] * 128 + (k - 256)];
        }
    }
}

// ---------------------------------------------------------------------------
// Pipelined fused-gather GEMM: out[M,N] = act(X[M,K] @ W[K,N] + b)
// BM=BN=128, BK=16, 256 thr, 8x8 outputs/thread as 8 m x 4 f32x2 n-PAIRS.
// R14: pair dimension moved M->N. W tile is PLAIN (w[n],w[n+1] is a natural
// 64-bit lane pair); X tile stores duplicated (x,x) pairs (X is the broadcast
// operand, dedup keeps reads at 1 wf/instr). SMEM read wavefronts/kk/warp:
// 10 -> 8; W fill STS halved. Double-buffered, one barrier per k-slab,
// __launch_bounds__(256,2) for 2 CTAs/SM.
// ---------------------------------------------------------------------------
template <int MODE, bool RELU>
__global__ void __launch_bounds__(256, 2)
gemm_kernel(int M, int K, int N,
            const float* __restrict__ W, const float* __restrict__ bias,
            int xsel, const float* Xdef, int ldx,
            int osel, float* Odef,
            const float* __restrict__ nodes,
            const int* __restrict__ erow, const int* __restrict__ ecol,
            const float* __restrict__ eattr,
            const float* __restrict__ u, const int* __restrict__ batch) {
    constexpr int BM = 128, BN = 128, BK = 16;
    constexpr int X2_LD = 256;   // doubled X row: [x0,x0,x1,x1,...]
    constexpr int WS_LD = 128;   // plain W row

    __shared__ __align__(16) float Xs2[2][BK * X2_LD];   // 2 x 16 KB
    __shared__ __align__(16) float Ws[2][BK * WS_LD];    // 2 x  8 KB (48 KB total)

    const float* X = cbuf_ptr(xsel, Xdef);
    float* out = buf_ptr(osel, Odef);

    const int tid = threadIdx.x;
    const int tx = tid & 15;               // n-group: 8 cols at n0
    const int ty = tid >> 4;               // m-group: 8 rows at m0
    const int n0 = tx * 8;
    const int m0 = ty * 8;
    const int blockM = blockIdx.y * BM;
    const int blockN = blockIdx.x * BN;

    unsigned long long acc[8][4];          // [m][n-pair]
#pragma unroll
    for (int i = 0; i < 8; ++i)
#pragma unroll
        for (int j = 0; j < 4; ++j) acc[i][j] = 0ull;

    const int T = K / BK;
    float4 xv[2];
    float4 wf[2];

    // W fill mapping: thread -> row kr = tid>>4 (0..15), cols wn0 = (tid&15)*8
    const int kr = tid >> 4;
    const int wn0 = (tid & 15) * 8;

    // ---- stage loaders (registers) ----
    auto load_frags = [&](int t) {
        const int k0 = t * BK;
        // X: 512 float4 = 128 m x 4 kq
#pragma unroll
        for (int it = 0; it < 2; ++it) {
            int f4 = tid + it * 256;
            int m = f4 >> 2;
            int kq = f4 & 3;
            int gm = blockM + m;
            if (gm < M)
                xv[it] = load_x4<MODE>(gm, k0 + kq * 4, X, ldx, nodes,
                                       erow, ecol, eattr, u, batch);
            else
                xv[it] = make_float4(0.f, 0.f, 0.f, 0.f);
        }
        // W: 16 rows x 128 cols; thread loads 8 contiguous floats of row kr
        const float* wrow = &W[(size_t)(k0 + kr) * N + blockN + wn0];
        wf[0] = *(const float4*)wrow;
        wf[1] = *(const float4*)(wrow + 4);
    };
    auto store_frags = [&](int b) {
        // X: store duplicated pairs, transposed [k][2m]
#pragma unroll
        for (int it = 0; it < 2; ++it) {
            int f4 = tid + it * 256;
            int m = f4 >> 2;
            int kq = f4 & 3;
            float* xs = &Xs2[b][(kq * 4) * X2_LD + 2 * m];
            *(float2*)&xs[0 * X2_LD] = make_float2(xv[it].x, xv[it].x);
            *(float2*)&xs[1 * X2_LD] = make_float2(xv[it].y, xv[it].y);
            *(float2*)&xs[2 * X2_LD] = make_float2(xv[it].z, xv[it].z);
            *(float2*)&xs[3 * X2_LD] = make_float2(xv[it].w, xv[it].w);
        }
        // W: plain contiguous store
        float* ws = &Ws[b][kr * WS_LD + wn0];
        *(float4*)ws = wf[0];
        *(float4*)(ws + 4) = wf[1];
    };

    // ---- prologue ----
    load_frags(0);
    store_frags(0);
    __syncthreads();

    // ---- mainloop: load(t+1) | compute(t) | store(t+1) | sync ----
    for (int t = 0; t < T; ++t) {
        const int cur = t & 1;
        if (t + 1 < T) load_frags(t + 1);

#pragma unroll
        for (int kk = 0; kk < BK; ++kk) {
            // X: 8 duplicated pairs (64B contiguous, broadcast across tx)
            const ulonglong2* xr = (const ulonglong2*)&Xs2[cur][kk * X2_LD + 2 * m0];
            ulonglong2 x01 = xr[0], x23 = xr[1], x45 = xr[2], x67 = xr[3];
            unsigned long long xp[8] = {x01.x, x01.y, x23.x, x23.y,
                                        x45.x, x45.y, x67.x, x67.y};
            // W: 4 natural pairs (32B contiguous per thread)
            const ulonglong2* wr = (const ulonglong2*)&Ws[cur][kk * WS_LD + n0];
            ulonglong2 wA = wr[0], wB = wr[1];
            unsigned long long wp[4] = {wA.x, wA.y, wB.x, wB.y};
#pragma unroll
            for (int i = 0; i < 8; ++i)
#pragma unroll
                for (int j = 0; j < 4; ++j) ffma2(acc[i][j], xp[i], wp[j]);
        }

        if (t + 1 < T) {
            store_frags(1 - cur);
            __syncthreads();
        }
    }

    // ---- epilogue: bias + act + store (2 contiguous float4 per row) ----
    float bv[8];
#pragma unroll
    for (int j = 0; j < 8; ++j) bv[j] = bias[blockN + n0 + j];

#pragma unroll
    for (int i = 0; i < 8; ++i) {
        int gm = blockM + m0 + i;
        if (gm >= M) continue;
        float vals[8];
#pragma unroll
        for (int j = 0; j < 4; ++j) {
            unsigned long long v = acc[i][j];
            float lo = __uint_as_float((unsigned int)v) + bv[2 * j];
            float hi = __uint_as_float((unsigned int)(v >> 32)) + bv[2 * j + 1];
            if (RELU) { lo = fmaxf(lo, 0.0f); hi = fmaxf(hi, 0.0f); }
            vals[2 * j] = lo;
            vals[2 * j + 1] = hi;
        }
        float4* o = (float4*)&out[(size_t)gm * N + blockN + n0];
        o[0] = make_float4(vals[0], vals[1], vals[2], vals[3]);
        o[1] = make_float4(vals[4], vals[5], vals[6], vals[7]);
    }
}

// ---------------------------------------------------------------------------
// Scatter kernels
// ---------------------------------------------------------------------------
__global__ void scatter_edges_kernel(const float* __restrict__ eo,
                                     const int* __restrict__ erow,
                                     const int* __restrict__ ecol,
                                     const int* __restrict__ batch) {
    long long idx = (long long)blockIdx.x * blockDim.x + threadIdx.x;
    if (idx >= (long long)N_EDGES * DIM) return;
    int e = (int)(idx >> 7);
    int d = (int)(idx & 127);
    float v = eo[idx];
    int c = ecol[e];
    atomicAdd(&g_agg[(size_t)c * 128 + d], v);
    int g = batch[erow[e]];
    atomicAdd(&g_gse[g * 128 + d], v);
    if (d == 0) {
        atomicAdd(&g_cnt[c], 1.0f);
        atomicAdd(&g_gce[g], 1.0f);
    }
}

__global__ void scatter_nodes_kernel(const float* __restrict__ no,
                                     const int* __restrict__ batch) {
    long long idx = (long long)blockIdx.x * blockDim.x + threadIdx.x;
    if (idx >= (long long)N_NODES * DIM) return;
    int n = (int)(idx >> 7);
    int d = (int)(idx & 127);
    float v = no[idx];
    int g = batch[n];
    atomicAdd(&g_gsn[g * 128 + d], v);
    if (d == 0) atomicAdd(&g_gcn[g], 1.0f);
}

__global__ void build_gin_kernel(const float* __restrict__ u) {
    int idx = blockIdx.x * blockDim.x + threadIdx.x;
    if (idx >= N_GRAPHS * 384) return;
    int g = idx / 384;
    int k = idx - g * 384;
    float v;
    if (k < 128) v = u[g * 128 + k];
    else if (k < 256) v = g_gsn[g * 128 + (k - 128)] / fmaxf(g_gcn[g], 1.0f);
    else v = g_gse[g * 128 + (k - 256)] / fmaxf(g_gce[g], 1.0f);
    g_gin[idx] = v;
}

// ---------------------------------------------------------------------------
// Tiny row-parallel global MLP
// ---------------------------------------------------------------------------
template <bool RELU>
__global__ void small_mlp_kernel(int xsel, int K, int N,
                                 const float* __restrict__ W, const float* __restrict__ b,
                                 int osel, float* Odef) {
    __shared__ float xs[384];
    const float* X = cbuf_ptr(xsel, nullptr);
    float* out;
    if (osel == 3) out = g_gh0;
    else if (osel == 4) out = g_gh1;
    else out = Odef;
    int g = blockIdx.x;
    for (int k = threadIdx.x; k < K; k += blockDim.x) xs[k] = X[g * K + k];
    __syncthreads();
    int n = threadIdx.x;
    float acc = b[n];
#pragma unroll 4
    for (int k = 0; k < K; ++k) acc += xs[k] * W[k * N + n];
    if (RELU) acc = fmaxf(acc, 0.0f);
    out[g * N + n] = acc;
}

// ---------------------------------------------------------------------------
// Launch: kernel launches ONLY
// ---------------------------------------------------------------------------
static inline int cdiv(int a, int b) { return (a + b - 1) / b; }

extern "C" void kernel_launch(void* const* d_in, const int* in_sizes, int n_in,
                              void* d_out, int out_size) {
    const float* nodes = (const float*)d_in[0];
    const int*   eidx  = (const int*)d_in[1];
    const float* eattr = (const float*)d_in[2];
    const float* u     = (const float*)d_in[3];
    const int*   batch = (const int*)d_in[4];

    const float* ew0 = (const float*)d_in[5];
    const float* eb0 = (const float*)d_in[6];
    const float* ew1 = (const float*)d_in[7];
    const float* eb1 = (const float*)d_in[8];
    const float* ew2 = (const float*)d_in[9];
    const float* eb2 = (const float*)d_in[10];
    const float* nw0 = (const float*)d_in[11];
    const float* nb0 = (const float*)d_in[12];
    const float* nw1 = (const float*)d_in[13];
    const float* nb1 = (const float*)d_in[14];
    const float* nw2 = (const float*)d_in[15];
    const float* nb2 = (const float*)d_in[16];
    const float* gw0 = (const float*)d_in[17];
    const float* gb0 = (const float*)d_in[18];
    const float* gw1 = (const float*)d_in[19];
    const float* gb1 = (const float*)d_in[20];
    const float* gw2 = (const float*)d_in[21];
    const float* gb2 = (const float*)d_in[22];

    const int* erow = eidx;
    const int* ecol = eidx + N_EDGES;

    float* out_nodes = (float*)d_out;
    float* out_edges = out_nodes + (size_t)N_NODES * DIM;
    float* out_glob  = out_edges + (size_t)N_EDGES * DIM;

    zero_all_kernel<<<cdiv(NZ_TOT, 256), 256>>>();

    // edge MLP: 512 -> 256 -> 256 -> 128
    {
        dim3 blk(256);
        dim3 g0(2, cdiv(N_EDGES, 128));
        gemm_kernel<1, true><<<g0, blk>>>(N_EDGES, 512, 256, ew0, eb0,
                                          -1, nullptr, 0, 0, nullptr,
                                          nodes, erow, ecol, eattr, u, batch);
        gemm_kernel<0, true><<<g0, blk>>>(N_EDGES, 256, 256, ew1, eb1,
                                          0, nullptr, 256, 1, nullptr,
                                          nullptr, nullptr, nullptr, nullptr,
                                          nullptr, nullptr);
        dim3 g1(1, cdiv(N_EDGES, 128));
        gemm_kernel<0, false><<<g1, blk>>>(N_EDGES, 256, 128, ew2, eb2,
                                           1, nullptr, 256, -1, out_edges,
                                           nullptr, nullptr, nullptr, nullptr,
                                           nullptr, nullptr);
    }

    {
        long long total = (long long)N_EDGES * DIM;
        scatter_edges_kernel<<<(int)((total + 255) / 256), 256>>>(out_edges, erow, ecol, batch);
    }

    // node MLP: 384 -> 256 -> 256 -> 128
    {
        dim3 blk(256);
        dim3 g0(2, cdiv(N_NODES, 128));
        gemm_kernel<2, true><<<g0, blk>>>(N_NODES, 384, 256, nw0, nb0,
                                          -1, nullptr, 0, 0, nullptr,
                                          nodes, nullptr, nullptr, nullptr,
                                          u, batch);
        gemm_kernel<0, true><<<g0, blk>>>(N_NODES, 256, 256, nw1, nb1,
                                          0, nullptr, 256, 1, nullptr,
                                          nullptr, nullptr, nullptr, nullptr,
                                          nullptr, nullptr);
        dim3 g1(1, cdiv(N_NODES, 128));
        gemm_kernel<0, false><<<g1, blk>>>(N_NODES, 256, 128, nw2, nb2,
                                           1, nullptr, 256, -1, out_nodes,
                                           nullptr, nullptr, nullptr, nullptr,
                                           nullptr, nullptr);
    }

    {
        long long total = (long long)N_NODES * DIM;
        scatter_nodes_kernel<<<(int)((total + 255) / 256), 256>>>(out_nodes, batch);
    }

    build_gin_kernel<<<cdiv(N_GRAPHS * 384, 256), 256>>>(u);

    small_mlp_kernel<true><<<N_GRAPHS, 256>>>(2, 384, 256, gw0, gb0, 3, nullptr);
    small_mlp_kernel<true><<<N_GRAPHS, 256>>>(3, 256, 256, gw1, gb1, 4, nullptr);
    small_mlp_kernel<false><<<N_GRAPHS, 128>>>(4, 256, 128, gw2, gb2, -1, out_glob);

    (void)in_sizes; (void)n_in; (void)out_size;
}

// round 16
// speedup vs baseline: 1.1677x; 1.1677x over previous
#include <cuda_runtime.h>
#include <cuda_bf16.h>
#include <cstdint>

#define N_NODES  30000
#define N_EDGES  300000
#define N_GRAPHS 128
#define DIM      128

// ---------------------------------------------------------------------------
// Scratch: __device__ globals, referenced ONLY from device code.
// ---------------------------------------------------------------------------
__device__ float g_bufA[(size_t)N_EDGES * 256];   // hidden ping
__device__ float g_bufB[(size_t)N_EDGES * 256];   // hidden pong
__device__ float g_agg[(size_t)N_NODES * DIM];    // scatter-sum of edges_out by col
__device__ float g_cnt[N_NODES];                  // edge count per node
__device__ float g_gsn[N_GRAPHS * DIM];           // per-graph node sums
__device__ float g_gse[N_GRAPHS * DIM];           // per-graph edge sums
__device__ float g_gcn[N_GRAPHS];                 // per-graph node counts
__device__ float g_gce[N_GRAPHS];                 // per-graph edge counts
__device__ float g_gin[N_GRAPHS * 384];           // global MLP input
__device__ float g_gh0[N_GRAPHS * 256];
__device__ float g_gh1[N_GRAPHS * 256];

__device__ __forceinline__ float* buf_ptr(int sel, float* def) {
    if (sel == 0) return g_bufA;
    if (sel == 1) return g_bufB;
    return def;
}
__device__ __forceinline__ const float* cbuf_ptr(int sel, const float* def) {
    if (sel == 0) return g_bufA;
    if (sel == 1) return g_bufB;
    if (sel == 2) return g_gin;
    if (sel == 3) return g_gh0;
    if (sel == 4) return g_gh1;
    return def;
}

// packed fp32x2 FMA
__device__ __forceinline__ void ffma2(unsigned long long& d,
                                      unsigned long long a,
                                      unsigned long long b) {
    asm("fma.rn.f32x2 %0, %1, %2, %0;" : "+l"(d) : "l"(a), "l"(b));
}

// cp.async 16B global->shared
__device__ __forceinline__ void cp_async16(uint32_t saddr, const void* gptr) {
    asm volatile("cp.async.ca.shared.global [%0], [%1], 16;"
                 :: "r"(saddr), "l"(gptr) : "memory");
}
__device__ __forceinline__ void cp_async_commit() {
    asm volatile("cp.async.commit_group;" ::: "memory");
}
__device__ __forceinline__ void cp_async_wait_all() {
    asm volatile("cp.async.wait_group 0;" ::: "memory");
}

// ---------------------------------------------------------------------------
// Zero accumulators
// ---------------------------------------------------------------------------
#define NZ_AGG (N_NODES * DIM)
#define NZ_1   (NZ_AGG + N_NODES)
#define NZ_2   (NZ_1 + N_GRAPHS * DIM)
#define NZ_3   (NZ_2 + N_GRAPHS * DIM)
#define NZ_4   (NZ_3 + N_GRAPHS)
#define NZ_TOT (NZ_4 + N_GRAPHS)

__global__ void zero_all_kernel() {
    int i = blockIdx.x * blockDim.x + threadIdx.x;
    if (i < NZ_AGG)      g_agg[i] = 0.0f;
    else if (i < NZ_1)   g_cnt[i - NZ_AGG] = 0.0f;
    else if (i < NZ_2)   g_gsn[i - NZ_1] = 0.0f;
    else if (i < NZ_3)   g_gse[i - NZ_2] = 0.0f;
    else if (i < NZ_4)   g_gcn[i - NZ_3] = 0.0f;
    else if (i < NZ_TOT) g_gce[i - NZ_4] = 0.0f;
}

// ---------------------------------------------------------------------------
// Vec4 gathered X loads (section boundaries multiples of 128; k0 multiple of
// BK=16 -> branch uniform per slab; aligned LDG.128).
// ---------------------------------------------------------------------------
template <int MODE>
__device__ __forceinline__ float4 load_x4(
    int m, int k, const float* __restrict__ X, int ldx,
    const float* __restrict__ nodes,
    const int* __restrict__ erow, const int* __restrict__ ecol,
    const float* __restrict__ eattr,
    const float* __restrict__ u, const int* __restrict__ batch) {
    if (MODE == 0) {
        return *(const float4*)&X[(size_t)m * ldx + k];
    } else if (MODE == 1) {
        if (k < 128) {
            return *(const float4*)&nodes[(size_t)erow[m] * 128 + k];
        } else if (k < 256) {
            return *(const float4*)&nodes[(size_t)ecol[m] * 128 + (k - 128)];
        } else if (k < 384) {
            return *(const float4*)&eattr[(size_t)m * 128 + (k - 256)];
        } else {
            return *(const float4*)&u[batch[erow[m]] * 128 + (k - 384)];
        }
    } else {
        if (k < 128) {
            return *(const float4*)&nodes[(size_t)m * 128 + k];
        } else if (k < 256) {
            float r = __frcp_rn(fmaxf(g_cnt[m], 1.0f));
            float4 a = *(const float4*)&g_agg[(size_t)m * 128 + (k - 128)];
            return make_float4(a.x * r, a.y * r, a.z * r, a.w * r);
        } else {
            return *(const float4*)&u[batch[m] * 128 + (k - 256)];
        }
    }
}

// ---------------------------------------------------------------------------
// Pipelined fused-gather GEMM: out[M,N] = act(X[M,K] @ W[K,N] + b)
// BM=BN=128, BK=16, 256 thr, 8m x 8n outputs/thread as 8m x 4 f32x2 n-pairs.
// R16 (banking-corrected pair-over-N):
//  - W tile = RAW row-major rows (natural u64 n-pairs), filled by cp.async
//    (no reg staging, no STS). Read as 4x LDS.64 at u64-index q*16+tx: lane
//    stride 8B -> 128B contiguous per instr -> conflict-free (4 wf/kk,
//    was 8 in R13; R14's 32B-lane-stride 4-way conflict FIXED).
//  - X tile duplicated (x,x) pairs [k][2m] (broadcast operand), LDG->STS,
//    read as 4x LDS.128 broadcast (1 wf each).
//  - Thread n-columns {32q+2tx+r} (same as R13 epilogue mapping).
// Double-buffered, one barrier per k-slab, __launch_bounds__(256,2).
// ---------------------------------------------------------------------------
template <int MODE, bool RELU>
__global__ void __launch_bounds__(256, 2)
gemm_kernel(int M, int K, int N,
            const float* __restrict__ W, const float* __restrict__ bias,
            int xsel, const float* Xdef, int ldx,
            int osel, float* Odef,
            const float* __restrict__ nodes,
            const int* __restrict__ erow, const int* __restrict__ ecol,
            const float* __restrict__ eattr,
            const float* __restrict__ u, const int* __restrict__ batch) {
    constexpr int BM = 128, BN = 128, BK = 16;
    constexpr int X2_LD = 256;   // doubled X row: [x0,x0,x1,x1,...]
    constexpr int WS_LD = 128;   // raw W row

    __shared__ __align__(16) float Xs2[2][BK * X2_LD];   // 2 x 16 KB
    __shared__ __align__(16) float Ws[2][BK * WS_LD];    // 2 x  8 KB (48 KB)

    const float* X = cbuf_ptr(xsel, Xdef);
    float* out = buf_ptr(osel, Odef);

    const int tid = threadIdx.x;
    const int tx = tid & 15;               // n-lane: pairs {q*16+tx}
    const int ty = tid >> 4;               // m-group: 8 rows at m0
    const int m0 = ty * 8;
    const int blockM = blockIdx.y * BM;
    const int blockN = blockIdx.x * BN;

    unsigned long long acc[8][4];          // [m][n-pair q]
#pragma unroll
    for (int i = 0; i < 8; ++i)
#pragma unroll
        for (int j = 0; j < 4; ++j) acc[i][j] = 0ull;

    const int T = K / BK;
    float4 xv[2];

    // W fill mapping: thread -> row tid>>4, float col (tid&15)*8 (two 16B)
    const int wr_row = tid >> 4;
    const int wr_col = (tid & 15) * 8;

    // ---- stage loaders ----
    auto load_frags = [&](int t, int b) {
        const int k0 = t * BK;
        // X: 512 float4 = 128 m x 4 kq  -> registers
#pragma unroll
        for (int it = 0; it < 2; ++it) {
            int f4 = tid + it * 256;
            int m = f4 >> 2;
            int kq = f4 & 3;
            int gm = blockM + m;
            if (gm < M)
                xv[it] = load_x4<MODE>(gm, k0 + kq * 4, X, ldx, nodes,
                                       erow, ecol, eattr, u, batch);
            else
                xv[it] = make_float4(0.f, 0.f, 0.f, 0.f);
        }
        // W: raw rows via cp.async (16 rows x 128 cols, 32B per thread)
        uint32_t ws = (uint32_t)__cvta_generic_to_shared(
            &Ws[b][wr_row * WS_LD + wr_col]);
        const float* wg = &W[(size_t)(k0 + wr_row) * N + blockN + wr_col];
        cp_async16(ws, wg);
        cp_async16(ws + 16, wg + 4);
        cp_async_commit();
    };
    auto store_x = [&](int b) {
        // X: store duplicated pairs, transposed [k][2m]
#pragma unroll
        for (int it = 0; it < 2; ++it) {
            int f4 = tid + it * 256;
            int m = f4 >> 2;
            int kq = f4 & 3;
            float* xs = &Xs2[b][(kq * 4) * X2_LD + 2 * m];
            *(float2*)&xs[0 * X2_LD] = make_float2(xv[it].x, xv[it].x);
            *(float2*)&xs[1 * X2_LD] = make_float2(xv[it].y, xv[it].y);
            *(float2*)&xs[2 * X2_LD] = make_float2(xv[it].z, xv[it].z);
            *(float2*)&xs[3 * X2_LD] = make_float2(xv[it].w, xv[it].w);
        }
    };

    // ---- prologue ----
    load_frags(0, 0);
    store_x(0);
    cp_async_wait_all();
    __syncthreads();

    // ---- mainloop: load(t+1) | compute(t) | store(t+1) | sync ----
    for (int t = 0; t < T; ++t) {
        const int cur = t & 1;
        if (t + 1 < T) load_frags(t + 1, 1 - cur);

#pragma unroll
        for (int kk = 0; kk < BK; ++kk) {
            // X: 8 duplicated pairs (64B contiguous, broadcast across tx)
            const ulonglong2* xr = (const ulonglong2*)&Xs2[cur][kk * X2_LD + 2 * m0];
            ulonglong2 x01 = xr[0], x23 = xr[1], x45 = xr[2], x67 = xr[3];
            unsigned long long xp[8] = {x01.x, x01.y, x23.x, x23.y,
                                        x45.x, x45.y, x67.x, x67.y};
            // W: 4 natural u64 pairs at u64-index q*16+tx (lane stride 8B)
            const unsigned long long* wk =
                (const unsigned long long*)&Ws[cur][kk * WS_LD];
            unsigned long long wp[4] = {wk[0 * 16 + tx], wk[1 * 16 + tx],
                                        wk[2 * 16 + tx], wk[3 * 16 + tx]};
#pragma unroll
            for (int i = 0; i < 8; ++i)
#pragma unroll
                for (int j = 0; j < 4; ++j) ffma2(acc[i][j], xp[i], wp[j]);
        }

        if (t + 1 < T) {
            store_x(1 - cur);
            cp_async_wait_all();
            __syncthreads();
        }
    }

    // ---- epilogue: bias + act + store (4x float2 per row) ----
    // thread's n column for (q, r): blockN + 32*q + 2*tx + r
    float bv[8];
#pragma unroll
    for (int q = 0; q < 4; ++q) {
        bv[2 * q]     = bias[blockN + 32 * q + 2 * tx];
        bv[2 * q + 1] = bias[blockN + 32 * q + 2 * tx + 1];
    }

#pragma unroll
    for (int i = 0; i < 8; ++i) {
        int gm = blockM + m0 + i;
        if (gm >= M) continue;
        float* orow = &out[(size_t)gm * N + blockN + 2 * tx];
#pragma unroll
        for (int q = 0; q < 4; ++q) {
            unsigned long long v = acc[i][q];
            float lo = __uint_as_float((unsigned int)v) + bv[2 * q];
            float hi = __uint_as_float((unsigned int)(v >> 32)) + bv[2 * q + 1];
            if (RELU) { lo = fmaxf(lo, 0.0f); hi = fmaxf(hi, 0.0f); }
            *(float2*)&orow[32 * q] = make_float2(lo, hi);
        }
    }
}

// ---------------------------------------------------------------------------
// Scatter kernels
// ---------------------------------------------------------------------------
__global__ void scatter_edges_kernel(const float* __restrict__ eo,
                                     const int* __restrict__ erow,
                                     const int* __restrict__ ecol,
                                     const int* __restrict__ batch) {
    long long idx = (long long)blockIdx.x * blockDim.x + threadIdx.x;
    if (idx >= (long long)N_EDGES * DIM) return;
    int e = (int)(idx >> 7);
    int d = (int)(idx & 127);
    float v = eo[idx];
    int c = ecol[e];
    atomicAdd(&g_agg[(size_t)c * 128 + d], v);
    int g = batch[erow[e]];
    atomicAdd(&g_gse[g * 128 + d], v);
    if (d == 0) {
        atomicAdd(&g_cnt[c], 1.0f);
        atomicAdd(&g_gce[g], 1.0f);
    }
}

__global__ void scatter_nodes_kernel(const float* __restrict__ no,
                                     const int* __restrict__ batch) {
    long long idx = (long long)blockIdx.x * blockDim.x + threadIdx.x;
    if (idx >= (long long)N_NODES * DIM) return;
    int n = (int)(idx >> 7);
    int d = (int)(idx & 127);
    float v = no[idx];
    int g = batch[n];
    atomicAdd(&g_gsn[g * 128 + d], v);
    if (d == 0) atomicAdd(&g_gcn[g], 1.0f);
}

__global__ void build_gin_kernel(const float* __restrict__ u) {
    int idx = blockIdx.x * blockDim.x + threadIdx.x;
    if (idx >= N_GRAPHS * 384) return;
    int g = idx / 384;
    int k = idx - g * 384;
    float v;
    if (k < 128) v = u[g * 128 + k];
    else if (k < 256) v = g_gsn[g * 128 + (k - 128)] / fmaxf(g_gcn[g], 1.0f);
    else v = g_gse[g * 128 + (k - 256)] / fmaxf(g_gce[g], 1.0f);
    g_gin[idx] = v;
}

// ---------------------------------------------------------------------------
// Tiny row-parallel global MLP
// ---------------------------------------------------------------------------
template <bool RELU>
__global__ void small_mlp_kernel(int xsel, int K, int N,
                                 const float* __restrict__ W, const float* __restrict__ b,
                                 int osel, float* Odef) {
    __shared__ float xs[384];
    const float* X = cbuf_ptr(xsel, nullptr);
    float* out;
    if (osel == 3) out = g_gh0;
    else if (osel == 4) out = g_gh1;
    else out = Odef;
    int g = blockIdx.x;
    for (int k = threadIdx.x; k < K; k += blockDim.x) xs[k] = X[g * K + k];
    __syncthreads();
    int n = threadIdx.x;
    float acc = b[n];
#pragma unroll 4
    for (int k = 0; k < K; ++k) acc += xs[k] * W[k * N + n];
    if (RELU) acc = fmaxf(acc, 0.0f);
    out[g * N + n] = acc;
}

// ---------------------------------------------------------------------------
// Launch: kernel launches ONLY
// ---------------------------------------------------------------------------
static inline int cdiv(int a, int b) { return (a + b - 1) / b; }

extern "C" void kernel_launch(void* const* d_in, const int* in_sizes, int n_in,
                              void* d_out, int out_size) {
    const float* nodes = (const float*)d_in[0];
    const int*   eidx  = (const int*)d_in[1];
    const float* eattr = (const float*)d_in[2];
    const float* u     = (const float*)d_in[3];
    const int*   batch = (const int*)d_in[4];

    const float* ew0 = (const float*)d_in[5];
    const float* eb0 = (const float*)d_in[6];
    const float* ew1 = (const float*)d_in[7];
    const float* eb1 = (const float*)d_in[8];
    const float* ew2 = (const float*)d_in[9];
    const float* eb2 = (const float*)d_in[10];
    const float* nw0 = (const float*)d_in[11];
    const float* nb0 = (const float*)d_in[12];
    const float* nw1 = (const float*)d_in[13];
    const float* nb1 = (const float*)d_in[14];
    const float* nw2 = (const float*)d_in[15];
    const float* nb2 = (const float*)d_in[16];
    const float* gw0 = (const float*)d_in[17];
    const float* gb0 = (const float*)d_in[18];
    const float* gw1 = (const float*)d_in[19];
    const float* gb1 = (const float*)d_in[20];
    const float* gw2 = (const float*)d_in[21];
    const float* gb2 = (const float*)d_in[22];

    const int* erow = eidx;
    const int* ecol = eidx + N_EDGES;

    float* out_nodes = (float*)d_out;
    float* out_edges = out_nodes + (size_t)N_NODES * DIM;
    float* out_glob  = out_edges + (size_t)N_EDGES * DIM;

    zero_all_kernel<<<cdiv(NZ_TOT, 256), 256>>>();

    // edge MLP: 512 -> 256 -> 256 -> 128
    {
        dim3 blk(256);
        dim3 g0(2, cdiv(N_EDGES, 128));
        gemm_kernel<1, true><<<g0, blk>>>(N_EDGES, 512, 256, ew0, eb0,
                                          -1, nullptr, 0, 0, nullptr,
                                          nodes, erow, ecol, eattr, u, batch);
        gemm_kernel<0, true><<<g0, blk>>>(N_EDGES, 256, 256, ew1, eb1,
                                          0, nullptr, 256, 1, nullptr,
                                          nullptr, nullptr, nullptr, nullptr,
                                          nullptr, nullptr);
        dim3 g1(1, cdiv(N_EDGES, 128));
        gemm_kernel<0, false><<<g1, blk>>>(N_EDGES, 256, 128, ew2, eb2,
                                           1, nullptr, 256, -1, out_edges,
                                           nullptr, nullptr, nullptr, nullptr,
                                           nullptr, nullptr);
    }

    {
        long long total = (long long)N_EDGES * DIM;
        scatter_edges_kernel<<<(int)((total + 255) / 256), 256>>>(out_edges, erow, ecol, batch);
    }

    // node MLP: 384 -> 256 -> 256 -> 128
    {
        dim3 blk(256);
        dim3 g0(2, cdiv(N_NODES, 128));
        gemm_kernel<2, true><<<g0, blk>>>(N_NODES, 384, 256, nw0, nb0,
                                          -1, nullptr, 0, 0, nullptr,
                                          nodes, nullptr, nullptr, nullptr,
                                          u, batch);
        gemm_kernel<0, true><<<g0, blk>>>(N_NODES, 256, 256, nw1, nb1,
                                          0, nullptr, 256, 1, nullptr,
                                          nullptr, nullptr, nullptr, nullptr,
                                          nullptr, nullptr);
        dim3 g1(1, cdiv(N_NODES, 128));
        gemm_kernel<0, false><<<g1, blk>>>(N_NODES, 256, 128, nw2, nb2,
                                           1, nullptr, 256, -1, out_nodes,
                                           nullptr, nullptr, nullptr, nullptr,
                                           nullptr, nullptr);
    }

    {
        long long total = (long long)N_NODES * DIM;
        scatter_nodes_kernel<<<(int)((total + 255) / 256), 256>>>(out_nodes, batch);
    }

    build_gin_kernel<<<cdiv(N_GRAPHS * 384, 256), 256>>>(u);

    small_mlp_kernel<true><<<N_GRAPHS, 256>>>(2, 384, 256, gw0, gb0, 3, nullptr);
    small_mlp_kernel<true><<<N_GRAPHS, 256>>>(3, 256, 256, gw1, gb1, 4, nullptr);
    small_mlp_kernel<false><<<N_GRAPHS, 128>>>(4, 256, 128, gw2, gb2, -1, out_glob);

    (void)in_sizes; (void)n_in; (void)out_size;
}